// round 5
// baseline (speedup 1.0000x reference)
#include <cuda_runtime.h>
#include <math.h>

// ---------------- problem constants ----------------
constexpr int B        = 16384;
constexpr int NM       = 64;    // models
constexpr int IN_F     = 6;
constexpr int OUT_F    = 3;
constexpr int HID      = 128;
constexpr int NFACT    = 4;

constexpr int MT       = 64;    // elements per tile
constexpr int XP       = 132;   // activation/weight smem pitch (floats)
constexpr int NTHREADS = 256;
constexpr int MAX_TILES = 16;

// output layout (float32, concatenated flattened tuple)
constexpr int OFF_IDX  = B * NFACT * OUT_F;   // 196608
constexpr int OFF_LOG  = OFF_IDX + B;         // 212992
constexpr int OFF_PROB = OFF_LOG + B * NM;    // 1261568

#define DINL __device__ __forceinline__

// ---------------- device scratch (no allocs allowed) ----------------
__device__ int g_idx[B];
__device__ int g_counts[NM];
__device__ int g_offsets[NM + 1];
__device__ int g_cursor[NM];
__device__ int g_order[B];

// ---------------- kernel 1: zero counts ----------------
__global__ void k_zero() {
    if (threadIdx.x < NM) g_counts[threadIdx.x] = 0;
}

// ---------------- kernel 2: select model index + easy outputs ----------------
// Reference pipeline (fp32): atan2 -> +2pi -> mod 2pi -> /2pi*64 -> floor.
// atan2 itself is computed in double and rounded to f32 == correctly-rounded
// f32 atan2 (what glibc/XLA produce); all later steps are IEEE-exact fp32 ops
// identical across platforms (fmodf is exact).
__global__ void k_select(const float* __restrict__ inp, float* __restrict__ out) {
    __shared__ int h[NM];
    if (threadIdx.x < NM) h[threadIdx.x] = 0;
    __syncthreads();

    int b = blockIdx.x * blockDim.x + threadIdx.x;  // grid covers exactly B
    float x0 = inp[b * 6 + 0];
    float x2 = inp[b * 6 + 2];
    const float TPf = 6.2831853071795864769f;
    float ang = (float)atan2((double)x2, (double)x0);  // correctly-rounded f32 atan2
    float t   = ang + TPf;
    float a   = fmodf(t, TPf);
    float v   = a / TPf * 64.0f;
    int idx = (int)floorf(v);
    idx = max(0, min(63, idx));

    g_idx[b] = idx;
    out[OFF_IDX + b] = (float)idx;

    atomicAdd(&h[idx], 1);
    __syncthreads();
    if (threadIdx.x < NM && h[threadIdx.x]) atomicAdd(&g_counts[threadIdx.x], h[threadIdx.x]);
}

// ---------------- kernel 3: fill logits / probabilities ----------------
__global__ void k_fill(float* __restrict__ out) {
    int i = blockIdx.x * blockDim.x + threadIdx.x;   // B*NM/4 threads
    float4 ones = make_float4(1.f, 1.f, 1.f, 1.f);
    float4 prob = make_float4(0.015625f, 0.015625f, 0.015625f, 0.015625f);
    ((float4*)(out + OFF_LOG))[i]  = ones;
    ((float4*)(out + OFF_PROB))[i] = prob;
}

// ---------------- kernel 4: scan counts -> offsets/cursor ----------------
__global__ void k_scan() {
    int t = threadIdx.x;            // 64 threads
    int c = g_counts[t];
    int v = c;
    #pragma unroll
    for (int d = 1; d < 32; d <<= 1) {
        int n = __shfl_up_sync(0xFFFFFFFFu, v, d);
        if ((t & 31) >= d) v += n;
    }
    __shared__ int ws[2];
    if ((t & 31) == 31) ws[t >> 5] = v;
    __syncthreads();
    if (t >= 32) v += ws[0];
    g_offsets[t + 1] = v;
    if (t == 0) g_offsets[0] = 0;
    g_cursor[t] = v - c;
}

// ---------------- kernel 5: scatter elements into model-sorted order ------
__global__ void k_scatter() {
    int b = blockIdx.x * blockDim.x + threadIdx.x;
    int idx = g_idx[b];
    int pos = atomicAdd(&g_cursor[idx], 1);
    g_order[pos] = b;
}

// ---------------- MLP helpers ----------------

// stage W (global [N][KS] row-major) -> smem K-major Ws[k*XP + n]
template<int Kc>
DINL void stage_w(const float* __restrict__ Wg, int KS, float* __restrict__ Ws, int Nn) {
    for (int g = threadIdx.x; g < Nn * Kc; g += NTHREADS) {
        int n = g / Kc;
        int k = g - n * Kc;
        Ws[k * XP + n] = Wg[n * KS + k];
    }
}

DINL void stage_b(const float* __restrict__ bg, float* __restrict__ Bs, int n) {
    for (int i = threadIdx.x; i < n; i += NTHREADS) Bs[i] = bg[i];
}

template<int K>
DINL void stage_wout(const float* __restrict__ Wg, float* __restrict__ Ws) {
    for (int g = threadIdx.x; g < OUT_F * K; g += NTHREADS) {
        int o = g / K;
        int k = g - o * K;
        Ws[o * XP + k] = Wg[o * HID + k];
    }
}

// fully-connected layer, relu. 256 threads: 16 neuron-groups x 16 elem-groups
template<int K, int N>
DINL void layer_fc(const float* __restrict__ Xin, float* __restrict__ Xout,
                   const float* __restrict__ Ws, const float* __restrict__ Bs) {
    constexpr int TN = N / 16;
    const int tx = threadIdx.x & 15;
    const int ty = threadIdx.x >> 4;
    const int n0 = tx * TN;
    const int e0 = ty * 4;

    float acc[4][TN];
    #pragma unroll
    for (int u = 0; u < TN; ++u) {
        float bv = Bs[n0 + u];
        #pragma unroll
        for (int j = 0; j < 4; ++j) acc[j][u] = bv;
    }

    if constexpr (K % 4 == 0) {
        #pragma unroll 2
        for (int k = 0; k < K; k += 4) {
            float xr[4][4];
            #pragma unroll
            for (int j = 0; j < 4; ++j) {
                float4 xv = *(const float4*)(Xin + (e0 + j) * XP + k);
                xr[j][0] = xv.x; xr[j][1] = xv.y; xr[j][2] = xv.z; xr[j][3] = xv.w;
            }
            #pragma unroll
            for (int kk = 0; kk < 4; ++kk) {
                const float* wr = Ws + (k + kk) * XP + n0;
                #pragma unroll
                for (int u2 = 0; u2 < TN / 2; ++u2) {
                    float2 w = *(const float2*)(wr + 2 * u2);
                    #pragma unroll
                    for (int j = 0; j < 4; ++j) {
                        acc[j][2 * u2]     = fmaf(xr[j][kk], w.x, acc[j][2 * u2]);
                        acc[j][2 * u2 + 1] = fmaf(xr[j][kk], w.y, acc[j][2 * u2 + 1]);
                    }
                }
            }
        }
    } else {
        #pragma unroll
        for (int k = 0; k < K; ++k) {
            const float* wr = Ws + k * XP + n0;
            float xk[4];
            #pragma unroll
            for (int j = 0; j < 4; ++j) xk[j] = Xin[(e0 + j) * XP + k];
            #pragma unroll
            for (int u2 = 0; u2 < TN / 2; ++u2) {
                float2 w = *(const float2*)(wr + 2 * u2);
                #pragma unroll
                for (int j = 0; j < 4; ++j) {
                    acc[j][2 * u2]     = fmaf(xk[j], w.x, acc[j][2 * u2]);
                    acc[j][2 * u2 + 1] = fmaf(xk[j], w.y, acc[j][2 * u2 + 1]);
                }
            }
        }
    }

    #pragma unroll
    for (int j = 0; j < 4; ++j) {
        #pragma unroll
        for (int u2 = 0; u2 < TN / 2; ++u2) {
            float2 o;
            o.x = fmaxf(acc[j][2 * u2], 0.f);
            o.y = fmaxf(acc[j][2 * u2 + 1], 0.f);
            *(float2*)(Xout + (e0 + j) * XP + n0 + 2 * u2) = o;
        }
    }
}

// output layer: K -> 3, no relu. 256 threads: 64 elems x 4 slots (o<3 active)
template<int K>
DINL void layer_out(const float* __restrict__ Xin, const float* __restrict__ Ws,
                    const float* __restrict__ Bs, float* __restrict__ out,
                    const int* __restrict__ ords, int cnt, int fi) {
    int e = threadIdx.x >> 2;
    int o = threadIdx.x & 3;
    if (o < 3) {
        float s = Bs[o];
        #pragma unroll 4
        for (int k = 0; k < K; k += 4) {
            float4 xv = *(const float4*)(Xin + e * XP + k);
            float4 wv = *(const float4*)(Ws + o * XP + k);
            s = fmaf(xv.x, wv.x, s);
            s = fmaf(xv.y, wv.y, s);
            s = fmaf(xv.z, wv.z, s);
            s = fmaf(xv.w, wv.w, s);
        }
        if (e < cnt) out[ords[e] * (NFACT * OUT_F) + fi * OUT_F + o] = s;
    }
}

template<int H>
DINL void mlp_body(const float* __restrict__ inp,
                   const float* __restrict__ W0, const float* __restrict__ b0,
                   const float* __restrict__ W1, const float* __restrict__ b1,
                   const float* __restrict__ W2, const float* __restrict__ b2,
                   const float* __restrict__ W3, const float* __restrict__ b3,
                   const float* __restrict__ W4, const float* __restrict__ b4,
                   float* __restrict__ out) {
    extern __shared__ float sm[];
    float* Xa = sm;                      // MT*XP
    float* Xb = Xa + MT * XP;            // MT*XP
    float* Ws = Xb + MT * XP;            // 128*XP (reserve max)
    float* Bs = Ws + HID * XP;           // 128
    int*   ords = (int*)(Bs + HID);      // MT ints

    constexpr int fi = H / 32 - 1;
    const int m = blockIdx.y;
    const int off0 = g_offsets[m];
    const int off1 = g_offsets[m + 1];

    for (int tile = blockIdx.x; off0 + tile * MT < off1; tile += gridDim.x) {
        const int beg = off0 + tile * MT;
        const int cnt = min(MT, off1 - beg);

        for (int i = threadIdx.x; i < MT; i += NTHREADS)
            ords[i] = (i < cnt) ? g_order[beg + i] : 0;
        __syncthreads();

        // load inputs (cols padded to 8, zero unused so garbage never flows)
        for (int i = threadIdx.x; i < MT * 8; i += NTHREADS) {
            int e = i >> 3, c = i & 7;
            Xa[e * XP + c] = (c < IN_F && e < cnt) ? inp[ords[e] * IN_F + c] : 0.f;
        }

        // layer 0: 6 -> H
        stage_w<IN_F>(W0 + m * (HID * IN_F), IN_F, Ws, H);
        stage_b(b0 + m * HID, Bs, H);
        __syncthreads();
        layer_fc<IN_F, H>(Xa, Xb, Ws, Bs);
        __syncthreads();

        // layer 1: H -> H
        stage_w<H>(W1 + m * (HID * HID), HID, Ws, H);
        stage_b(b1 + m * HID, Bs, H);
        __syncthreads();
        layer_fc<H, H>(Xb, Xa, Ws, Bs);
        __syncthreads();

        // layer 2
        stage_w<H>(W2 + m * (HID * HID), HID, Ws, H);
        stage_b(b2 + m * HID, Bs, H);
        __syncthreads();
        layer_fc<H, H>(Xa, Xb, Ws, Bs);
        __syncthreads();

        // layer 3
        stage_w<H>(W3 + m * (HID * HID), HID, Ws, H);
        stage_b(b3 + m * HID, Bs, H);
        __syncthreads();
        layer_fc<H, H>(Xb, Xa, Ws, Bs);
        __syncthreads();

        // output layer: H -> 3
        stage_wout<H>(W4 + m * (OUT_F * HID), Ws);
        if (threadIdx.x < OUT_F) Bs[threadIdx.x] = b4[m * OUT_F + threadIdx.x];
        __syncthreads();
        layer_out<H>(Xa, Ws, Bs, out, ords, cnt, fi);
        __syncthreads();
    }
}

__global__ __launch_bounds__(NTHREADS, 1) void k_mlp_all(
    const float* __restrict__ inp,
    const float* __restrict__ W0, const float* __restrict__ b0,
    const float* __restrict__ W1, const float* __restrict__ b1,
    const float* __restrict__ W2, const float* __restrict__ b2,
    const float* __restrict__ W3, const float* __restrict__ b3,
    const float* __restrict__ W4, const float* __restrict__ b4,
    float* __restrict__ out) {
    switch (blockIdx.z) {
        case 0: mlp_body<32 >(inp, W0, b0, W1, b1, W2, b2, W3, b3, W4, b4, out); break;
        case 1: mlp_body<64 >(inp, W0, b0, W1, b1, W2, b2, W3, b3, W4, b4, out); break;
        case 2: mlp_body<96 >(inp, W0, b0, W1, b1, W2, b2, W3, b3, W4, b4, out); break;
        default: mlp_body<128>(inp, W0, b0, W1, b1, W2, b2, W3, b3, W4, b4, out); break;
    }
}

// ---------------- launch ----------------
extern "C" void kernel_launch(void* const* d_in, const int* in_sizes, int n_in,
                              void* d_out, int out_size) {
    const float* inp = (const float*)d_in[0];
    const float* W0  = (const float*)d_in[1];
    const float* b0  = (const float*)d_in[2];
    const float* W1  = (const float*)d_in[3];
    const float* b1  = (const float*)d_in[4];
    const float* W2  = (const float*)d_in[5];
    const float* b2  = (const float*)d_in[6];
    const float* W3  = (const float*)d_in[7];
    const float* b3  = (const float*)d_in[8];
    const float* W4  = (const float*)d_in[9];
    const float* b4  = (const float*)d_in[10];
    float* out = (float*)d_out;

    k_zero<<<1, 64>>>();
    k_select<<<B / NTHREADS, NTHREADS>>>(inp, out);
    k_fill<<<(B * NM / 4) / NTHREADS, NTHREADS>>>(out);
    k_scan<<<1, 64>>>();
    k_scatter<<<B / NTHREADS, NTHREADS>>>();

    size_t smem = (size_t)(2 * MT * XP + HID * XP + HID) * sizeof(float) + MT * sizeof(int);
    cudaFuncSetAttribute(k_mlp_all, cudaFuncAttributeMaxDynamicSharedMemorySize, (int)smem);
    dim3 grid(MAX_TILES, NM, NFACT);
    k_mlp_all<<<grid, NTHREADS, smem>>>(inp, W0, b0, W1, b1, W2, b2, W3, b3, W4, b4, out);
}

// round 6
// speedup vs baseline: 1.1048x; 1.1048x over previous
#include <cuda_runtime.h>
#include <math.h>

// ---------------- problem constants ----------------
constexpr int B        = 16384;
constexpr int NM       = 64;    // models
constexpr int IN_F     = 6;
constexpr int OUT_F    = 3;
constexpr int HID      = 128;
constexpr int NFACT    = 4;

constexpr int MT       = 128;   // elements per tile
constexpr int XP       = 132;   // activation/weight smem pitch (floats)
constexpr int NTHREADS = 256;
constexpr int MAX_TILES = 4;

// output layout (float32, concatenated flattened tuple)
constexpr int OFF_IDX  = B * NFACT * OUT_F;   // 196608
constexpr int OFF_LOG  = OFF_IDX + B;         // 212992
constexpr int OFF_PROB = OFF_LOG + B * NM;    // 1261568

#define DINL __device__ __forceinline__

// ---------------- f32x2 packed math (sm_100+) ----------------
DINL unsigned long long pack2(float lo, float hi) {
    unsigned long long r;
    asm("mov.b64 %0, {%1, %2};" : "=l"(r) : "f"(lo), "f"(hi));
    return r;
}
DINL void unpack2(unsigned long long v, float& lo, float& hi) {
    asm("mov.b64 {%0, %1}, %2;" : "=f"(lo), "=f"(hi) : "l"(v));
}
DINL unsigned long long fma2(unsigned long long a, unsigned long long b, unsigned long long c) {
    unsigned long long d;
    asm("fma.rn.f32x2 %0, %1, %2, %3;" : "=l"(d) : "l"(a), "l"(b), "l"(c));
    return d;
}

// ---------------- device scratch (no allocs allowed) ----------------
__device__ int g_idx[B];
__device__ int g_counts[NM];
__device__ int g_offsets[NM + 1];
__device__ int g_cursor[NM];
__device__ int g_order[B];

// ---------------- kernel 1: zero counts ----------------
__global__ void k_zero() {
    if (threadIdx.x < NM) g_counts[threadIdx.x] = 0;
}

// ---------------- kernel 2: select model index + easy outputs ----------------
// Reference fp32 pipeline; atan2 computed in double then rounded to f32 ==
// correctly-rounded f32 atan2 (matches the reference's atan2). Later steps are
// IEEE-exact fp32 ops identical across platforms.
__global__ void k_select(const float* __restrict__ inp, float* __restrict__ out) {
    __shared__ int h[NM];
    if (threadIdx.x < NM) h[threadIdx.x] = 0;
    __syncthreads();

    int b = blockIdx.x * blockDim.x + threadIdx.x;  // grid covers exactly B
    float x0 = inp[b * 6 + 0];
    float x2 = inp[b * 6 + 2];
    const float TPf = 6.2831853071795864769f;
    float ang = (float)atan2((double)x2, (double)x0);  // correctly-rounded f32 atan2
    float t   = ang + TPf;
    float a   = fmodf(t, TPf);
    float v   = a / TPf * 64.0f;
    int idx = (int)floorf(v);
    idx = max(0, min(63, idx));

    g_idx[b] = idx;
    out[OFF_IDX + b] = (float)idx;

    atomicAdd(&h[idx], 1);
    __syncthreads();
    if (threadIdx.x < NM && h[threadIdx.x]) atomicAdd(&g_counts[threadIdx.x], h[threadIdx.x]);
}

// ---------------- kernel 3: fill logits / probabilities ----------------
__global__ void k_fill(float* __restrict__ out) {
    int i = blockIdx.x * blockDim.x + threadIdx.x;   // B*NM/4 threads
    float4 ones = make_float4(1.f, 1.f, 1.f, 1.f);
    float4 prob = make_float4(0.015625f, 0.015625f, 0.015625f, 0.015625f);
    ((float4*)(out + OFF_LOG))[i]  = ones;
    ((float4*)(out + OFF_PROB))[i] = prob;
}

// ---------------- kernel 4: scan counts -> offsets/cursor ----------------
__global__ void k_scan() {
    int t = threadIdx.x;            // 64 threads
    int c = g_counts[t];
    int v = c;
    #pragma unroll
    for (int d = 1; d < 32; d <<= 1) {
        int n = __shfl_up_sync(0xFFFFFFFFu, v, d);
        if ((t & 31) >= d) v += n;
    }
    __shared__ int ws[2];
    if ((t & 31) == 31) ws[t >> 5] = v;
    __syncthreads();
    if (t >= 32) v += ws[0];
    g_offsets[t + 1] = v;
    if (t == 0) g_offsets[0] = 0;
    g_cursor[t] = v - c;
}

// ---------------- kernel 5: scatter elements into model-sorted order ------
__global__ void k_scatter() {
    int b = blockIdx.x * blockDim.x + threadIdx.x;
    int idx = g_idx[b];
    int pos = atomicAdd(&g_cursor[idx], 1);
    g_order[pos] = b;
}

// ---------------- chunked load/store helpers ----------------
template<int C>
DINL void loadchunk(const float* __restrict__ p, float* __restrict__ w) {
    if constexpr (C == 4) { float4 v = *(const float4*)p; w[0]=v.x; w[1]=v.y; w[2]=v.z; w[3]=v.w; }
    else if constexpr (C == 3) { w[0]=p[0]; w[1]=p[1]; w[2]=p[2]; }
    else if constexpr (C == 2) { float2 v = *(const float2*)p; w[0]=v.x; w[1]=v.y; }
    else { w[0] = p[0]; }
}
template<int C>
DINL void storechunk(float* __restrict__ p, const float* __restrict__ w) {
    if constexpr (C == 4) { float4 v; v.x=w[0]; v.y=w[1]; v.z=w[2]; v.w=w[3]; *(float4*)p = v; }
    else if constexpr (C == 3) { p[0]=w[0]; p[1]=w[1]; p[2]=w[2]; }
    else if constexpr (C == 2) { float2 v; v.x=w[0]; v.y=w[1]; *(float2*)p = v; }
    else { p[0] = w[0]; }
}

// ---------------- MLP staging ----------------

// stage W (global [N][KS] row-major) -> smem K-major Ws[k*XP + n]
template<int Kc>
DINL void stage_w(const float* __restrict__ Wg, int KS, float* __restrict__ Ws, int Nn) {
    for (int g = threadIdx.x; g < Nn * Kc; g += NTHREADS) {
        int n = g / Kc;
        int k = g - n * Kc;
        Ws[k * XP + n] = Wg[n * KS + k];
    }
}

DINL void stage_b(const float* __restrict__ bg, float* __restrict__ Bs, int n) {
    for (int i = threadIdx.x; i < n; i += NTHREADS) Bs[i] = bg[i];
}

template<int K>
DINL void stage_wout(const float* __restrict__ Wg, float* __restrict__ Ws) {
    for (int g = threadIdx.x; g < OUT_F * K; g += NTHREADS) {
        int o = g / K;
        int k = g - o * K;
        Ws[o * XP + k] = Wg[o * HID + k];
    }
}

// ---------------- fused FC layer, relu, f32x2 ----------------
// 256 threads: tx (16 neuron groups) x ty (16 element groups of 8).
// Thread owns two contiguous neuron chunks of C = N/32 floats:
//   chunk A at n = C*tx, chunk B at n = N/2 + C*tx  -> warp W loads contiguous.
template<int K, int N>
DINL void layer_fc(const float* __restrict__ Xin, float* __restrict__ Xout,
                   const float* __restrict__ Ws, const float* __restrict__ Bs) {
    constexpr int C  = N / 32;   // floats per chunk
    constexpr int TN = 2 * C;    // neurons per thread
    const int tx = threadIdx.x & 15;
    const int ty = threadIdx.x >> 4;
    const int e0 = ty * 8;
    const int nA = C * tx;
    const int nB = N / 2 + C * tx;

    unsigned long long acc[8][C];
    {
        float bv[TN];
        loadchunk<C>(Bs + nA, bv);
        loadchunk<C>(Bs + nB, bv + C);
        #pragma unroll
        for (int p = 0; p < C; ++p) {
            unsigned long long bp = pack2(bv[2 * p], bv[2 * p + 1]);
            #pragma unroll
            for (int j = 0; j < 8; ++j) acc[j][p] = bp;
        }
    }

    if constexpr (K % 4 == 0) {
        #pragma unroll 2
        for (int k = 0; k < K; k += 4) {
            float xr[8][4];
            #pragma unroll
            for (int j = 0; j < 8; ++j) {
                float4 xv = *(const float4*)(Xin + (e0 + j) * XP + k);
                xr[j][0] = xv.x; xr[j][1] = xv.y; xr[j][2] = xv.z; xr[j][3] = xv.w;
            }
            #pragma unroll
            for (int kk = 0; kk < 4; ++kk) {
                float wv[TN];
                loadchunk<C>(Ws + (k + kk) * XP + nA, wv);
                loadchunk<C>(Ws + (k + kk) * XP + nB, wv + C);
                unsigned long long wp[C];
                #pragma unroll
                for (int p = 0; p < C; ++p) wp[p] = pack2(wv[2 * p], wv[2 * p + 1]);
                #pragma unroll
                for (int j = 0; j < 8; ++j) {
                    unsigned long long xx = pack2(xr[j][kk], xr[j][kk]);
                    #pragma unroll
                    for (int p = 0; p < C; ++p) acc[j][p] = fma2(xx, wp[p], acc[j][p]);
                }
            }
        }
    } else {
        #pragma unroll
        for (int k = 0; k < K; ++k) {
            float wv[TN];
            loadchunk<C>(Ws + k * XP + nA, wv);
            loadchunk<C>(Ws + k * XP + nB, wv + C);
            unsigned long long wp[C];
            #pragma unroll
            for (int p = 0; p < C; ++p) wp[p] = pack2(wv[2 * p], wv[2 * p + 1]);
            #pragma unroll
            for (int j = 0; j < 8; ++j) {
                float xk = Xin[(e0 + j) * XP + k];
                unsigned long long xx = pack2(xk, xk);
                #pragma unroll
                for (int p = 0; p < C; ++p) acc[j][p] = fma2(xx, wp[p], acc[j][p]);
            }
        }
    }

    #pragma unroll
    for (int j = 0; j < 8; ++j) {
        float ov[TN];
        #pragma unroll
        for (int p = 0; p < C; ++p) unpack2(acc[j][p], ov[2 * p], ov[2 * p + 1]);
        #pragma unroll
        for (int i = 0; i < TN; ++i) ov[i] = fmaxf(ov[i], 0.f);
        storechunk<C>(Xout + (e0 + j) * XP + nA, ov);
        storechunk<C>(Xout + (e0 + j) * XP + nB, ov + C);
    }
}

// output layer: K -> 3, no relu. MT*3 work items over 256 threads.
template<int K>
DINL void layer_out(const float* __restrict__ Xin, const float* __restrict__ Ws,
                    const float* __restrict__ Bs, float* __restrict__ out,
                    const int* __restrict__ ords, int cnt, int fi) {
    for (int idx = threadIdx.x; idx < MT * OUT_F; idx += NTHREADS) {
        int e = idx / 3;
        int o = idx - 3 * e;
        float s = Bs[o];
        #pragma unroll 4
        for (int k = 0; k < K; k += 4) {
            float4 xv = *(const float4*)(Xin + e * XP + k);
            float4 wv = *(const float4*)(Ws + o * XP + k);
            s = fmaf(xv.x, wv.x, s);
            s = fmaf(xv.y, wv.y, s);
            s = fmaf(xv.z, wv.z, s);
            s = fmaf(xv.w, wv.w, s);
        }
        if (e < cnt) out[ords[e] * (NFACT * OUT_F) + fi * OUT_F + o] = s;
    }
}

template<int H>
DINL void mlp_body(const float* __restrict__ inp,
                   const float* __restrict__ W0, const float* __restrict__ b0,
                   const float* __restrict__ W1, const float* __restrict__ b1,
                   const float* __restrict__ W2, const float* __restrict__ b2,
                   const float* __restrict__ W3, const float* __restrict__ b3,
                   const float* __restrict__ W4, const float* __restrict__ b4,
                   float* __restrict__ out) {
    extern __shared__ float sm[];
    float* Xa = sm;                      // MT*XP
    float* Xb = Xa + MT * XP;            // MT*XP
    float* Ws = Xb + MT * XP;            // HID*XP
    float* Bs = Ws + HID * XP;           // HID
    int*   ords = (int*)(Bs + HID);      // MT ints

    constexpr int fi = H / 32 - 1;
    const int m = blockIdx.y;
    const int off0 = g_offsets[m];
    const int off1 = g_offsets[m + 1];

    for (int tile = blockIdx.x; off0 + tile * MT < off1; tile += MAX_TILES) {
        const int beg = off0 + tile * MT;
        const int cnt = min(MT, off1 - beg);

        for (int i = threadIdx.x; i < MT; i += NTHREADS)
            ords[i] = (i < cnt) ? g_order[beg + i] : 0;
        __syncthreads();

        // load inputs (cols padded to 8, zero unused so garbage never flows)
        for (int i = threadIdx.x; i < MT * 8; i += NTHREADS) {
            int e = i >> 3, c = i & 7;
            Xa[e * XP + c] = (c < IN_F && e < cnt) ? inp[ords[e] * IN_F + c] : 0.f;
        }

        // layer 0: 6 -> H
        stage_w<IN_F>(W0 + m * (HID * IN_F), IN_F, Ws, H);
        stage_b(b0 + m * HID, Bs, H);
        __syncthreads();
        layer_fc<IN_F, H>(Xa, Xb, Ws, Bs);
        __syncthreads();

        // layer 1: H -> H
        stage_w<H>(W1 + m * (HID * HID), HID, Ws, H);
        stage_b(b1 + m * HID, Bs, H);
        __syncthreads();
        layer_fc<H, H>(Xb, Xa, Ws, Bs);
        __syncthreads();

        // layer 2
        stage_w<H>(W2 + m * (HID * HID), HID, Ws, H);
        stage_b(b2 + m * HID, Bs, H);
        __syncthreads();
        layer_fc<H, H>(Xa, Xb, Ws, Bs);
        __syncthreads();

        // layer 3
        stage_w<H>(W3 + m * (HID * HID), HID, Ws, H);
        stage_b(b3 + m * HID, Bs, H);
        __syncthreads();
        layer_fc<H, H>(Xb, Xa, Ws, Bs);
        __syncthreads();

        // output layer: H -> 3
        stage_wout<H>(W4 + m * (OUT_F * HID), Ws);
        if (threadIdx.x < OUT_F) Bs[threadIdx.x] = b4[m * OUT_F + threadIdx.x];
        __syncthreads();
        layer_out<H>(Xa, Ws, Bs, out, ords, cnt, fi);
        __syncthreads();
    }
}

__global__ __launch_bounds__(NTHREADS, 1) void k_mlp_all(
    const float* __restrict__ inp,
    const float* __restrict__ W0, const float* __restrict__ b0,
    const float* __restrict__ W1, const float* __restrict__ b1,
    const float* __restrict__ W2, const float* __restrict__ b2,
    const float* __restrict__ W3, const float* __restrict__ b3,
    const float* __restrict__ W4, const float* __restrict__ b4,
    float* __restrict__ out) {
    switch (blockIdx.z) {
        case 0: mlp_body<32 >(inp, W0, b0, W1, b1, W2, b2, W3, b3, W4, b4, out); break;
        case 1: mlp_body<64 >(inp, W0, b0, W1, b1, W2, b2, W3, b3, W4, b4, out); break;
        case 2: mlp_body<96 >(inp, W0, b0, W1, b1, W2, b2, W3, b3, W4, b4, out); break;
        default: mlp_body<128>(inp, W0, b0, W1, b1, W2, b2, W3, b3, W4, b4, out); break;
    }
}

// ---------------- launch ----------------
extern "C" void kernel_launch(void* const* d_in, const int* in_sizes, int n_in,
                              void* d_out, int out_size) {
    const float* inp = (const float*)d_in[0];
    const float* W0  = (const float*)d_in[1];
    const float* b0  = (const float*)d_in[2];
    const float* W1  = (const float*)d_in[3];
    const float* b1  = (const float*)d_in[4];
    const float* W2  = (const float*)d_in[5];
    const float* b2  = (const float*)d_in[6];
    const float* W3  = (const float*)d_in[7];
    const float* b3  = (const float*)d_in[8];
    const float* W4  = (const float*)d_in[9];
    const float* b4  = (const float*)d_in[10];
    float* out = (float*)d_out;

    k_zero<<<1, 64>>>();
    k_select<<<B / NTHREADS, NTHREADS>>>(inp, out);
    k_fill<<<(B * NM / 4) / NTHREADS, NTHREADS>>>(out);
    k_scan<<<1, 64>>>();
    k_scatter<<<B / NTHREADS, NTHREADS>>>();

    size_t smem = (size_t)(2 * MT * XP + HID * XP + HID) * sizeof(float) + MT * sizeof(int);
    cudaFuncSetAttribute(k_mlp_all, cudaFuncAttributeMaxDynamicSharedMemorySize, (int)smem);
    dim3 grid(MAX_TILES, NM, NFACT);
    k_mlp_all<<<grid, NTHREADS, smem>>>(inp, W0, b0, W1, b1, W2, b2, W3, b3, W4, b4, out);
}

// round 9
// speedup vs baseline: 2.1115x; 1.9111x over previous
#include <cuda_runtime.h>
#include <cstdint>
#include <math.h>

// ---------------- problem constants ----------------
constexpr int B        = 16384;
constexpr int NM       = 64;
constexpr int IN_F     = 6;
constexpr int OUT_F    = 3;
constexpr int HID      = 128;
constexpr int NFACT    = 4;

constexpr int MT       = 128;   // elements per tile (MMA M)
constexpr int XP       = 132;   // smem pitch (floats): conflict-free for frag patterns
constexpr int NTHREADS = 256;   // 8 warps x 16 rows = 128 elements
constexpr int NT_X     = 2;     // CTAs per (model, factor)

constexpr int OFF_IDX  = B * NFACT * OUT_F;
constexpr int OFF_LOG  = OFF_IDX + B;
constexpr int OFF_PROB = OFF_LOG + B * NM;

#define DINL __device__ __forceinline__

// ---------------- device scratch ----------------
__device__ int g_idx[B];
__device__ int g_counts[NM];
__device__ int g_offsets[NM + 1];
__device__ int g_cursor[NM];
__device__ int g_order[B];

// ---------------- prologue kernels (unchanged, passing) ----------------
__global__ void k_zero() {
    if (threadIdx.x < NM) g_counts[threadIdx.x] = 0;
}

__global__ void k_select(const float* __restrict__ inp, float* __restrict__ out) {
    __shared__ int h[NM];
    if (threadIdx.x < NM) h[threadIdx.x] = 0;
    __syncthreads();

    int b = blockIdx.x * blockDim.x + threadIdx.x;
    float x0 = inp[b * 6 + 0];
    float x2 = inp[b * 6 + 2];
    const float TPf = 6.2831853071795864769f;
    float ang = (float)atan2((double)x2, (double)x0);  // correctly-rounded f32 atan2
    float t   = ang + TPf;
    float a   = fmodf(t, TPf);
    float v   = a / TPf * 64.0f;
    int idx = (int)floorf(v);
    idx = max(0, min(63, idx));

    g_idx[b] = idx;
    out[OFF_IDX + b] = (float)idx;

    atomicAdd(&h[idx], 1);
    __syncthreads();
    if (threadIdx.x < NM && h[threadIdx.x]) atomicAdd(&g_counts[threadIdx.x], h[threadIdx.x]);
}

__global__ void k_fill(float* __restrict__ out) {
    int i = blockIdx.x * blockDim.x + threadIdx.x;
    float4 ones = make_float4(1.f, 1.f, 1.f, 1.f);
    float4 prob = make_float4(0.015625f, 0.015625f, 0.015625f, 0.015625f);
    ((float4*)(out + OFF_LOG))[i]  = ones;
    ((float4*)(out + OFF_PROB))[i] = prob;
}

__global__ void k_scan() {
    int t = threadIdx.x;
    int c = g_counts[t];
    int v = c;
    #pragma unroll
    for (int d = 1; d < 32; d <<= 1) {
        int n = __shfl_up_sync(0xFFFFFFFFu, v, d);
        if ((t & 31) >= d) v += n;
    }
    __shared__ int ws[2];
    if ((t & 31) == 31) ws[t >> 5] = v;
    __syncthreads();
    if (t >= 32) v += ws[0];
    g_offsets[t + 1] = v;
    if (t == 0) g_offsets[0] = 0;
    g_cursor[t] = v - c;
}

__global__ void k_scatter() {
    int b = blockIdx.x * blockDim.x + threadIdx.x;
    int idx = g_idx[b];
    int pos = atomicAdd(&g_cursor[idx], 1);
    g_order[pos] = b;
}

// ---------------- tf32 helpers ----------------
DINL uint32_t tf32u(float x) {            // cvt.rna.tf32 -> b32 bits
    uint32_t r;
    asm("cvt.rna.tf32.f32 %0, %1;" : "=r"(r) : "f"(x));
    return r;
}
DINL float tf32f(float x) { return __uint_as_float(tf32u(x)); }

// mma.sync m16n8k8 tf32: D += A*B  (A row-major 16x8, B col-major 8x8, fp32 acc)
DINL void mma8(float& c0, float& c1, float& c2, float& c3,
               uint32_t a0, uint32_t a1, uint32_t a2, uint32_t a3,
               uint32_t b0, uint32_t b1) {
    asm volatile(
        "mma.sync.aligned.m16n8k8.row.col.f32.tf32.tf32.f32 "
        "{%0,%1,%2,%3}, {%4,%5,%6,%7}, {%8,%9}, {%0,%1,%2,%3};"
        : "+f"(c0), "+f"(c1), "+f"(c2), "+f"(c3)
        : "r"(a0), "r"(a1), "r"(a2), "r"(a3), "r"(b0), "r"(b1));
}

// ---------------- fused FC layer via warp MMA ----------------
// Fragment mapping (m16n8k8.row.col):
//   g = lane>>2, tig = lane&3
//   A: a0=(row g, col tig) a1=(g+8, tig) a2=(g, tig+4) a3=(g+8, tig+4)
//   B: b0=(k tig, n gcol)  b1=(k tig+4, n gcol)       [B[k][n] = W[n][k]]
//   D: c0=(g, 2tig) c1=(g, 2tig+1) c2=(g+8, 2tig) c3=(g+8, 2tig+1)
// Warps own disjoint 16-row slices; all read the same Ws.
template<int KC, int NC>
DINL void layer_fc(const float* __restrict__ Xin, float* __restrict__ Xout,
                   const float* __restrict__ Ws, const float* __restrict__ Bs,
                   int e0, int g, int tig) {
    // preload A fragments for all K chunks
    uint32_t a[KC][4];
    #pragma unroll
    for (int kc = 0; kc < KC; ++kc) {
        const float* xr = Xin + (e0 + g) * XP + kc * 8 + tig;
        a[kc][0] = __float_as_uint(xr[0]);
        a[kc][2] = __float_as_uint(xr[4]);
        a[kc][1] = __float_as_uint(xr[8 * XP]);
        a[kc][3] = __float_as_uint(xr[8 * XP + 4]);
    }
    // two n-chunks in flight for MMA ILP
    #pragma unroll
    for (int nc = 0; nc < NC; nc += 2) {
        const int n0 = nc * 8, n1 = n0 + 8;
        float2 bia0 = *(const float2*)(Bs + n0 + 2 * tig);
        float2 bia1 = *(const float2*)(Bs + n1 + 2 * tig);
        float c0[4] = { bia0.x, bia0.y, bia0.x, bia0.y };
        float c1[4] = { bia1.x, bia1.y, bia1.x, bia1.y };
        #pragma unroll
        for (int kc = 0; kc < KC; ++kc) {
            const float* w0 = Ws + (n0 + g) * XP + kc * 8 + tig;
            const float* w1 = Ws + (n1 + g) * XP + kc * 8 + tig;
            uint32_t b00 = __float_as_uint(w0[0]), b01 = __float_as_uint(w0[4]);
            uint32_t b10 = __float_as_uint(w1[0]), b11 = __float_as_uint(w1[4]);
            mma8(c0[0], c0[1], c0[2], c0[3], a[kc][0], a[kc][1], a[kc][2], a[kc][3], b00, b01);
            mma8(c1[0], c1[1], c1[2], c1[3], a[kc][0], a[kc][1], a[kc][2], a[kc][3], b10, b11);
        }
        // relu + tf32 round + store (cols 2tig, 2tig+1 contiguous)
        float2 v;
        v.x = tf32f(fmaxf(c0[0], 0.f)); v.y = tf32f(fmaxf(c0[1], 0.f));
        *(float2*)(Xout + (e0 + g) * XP + n0 + 2 * tig) = v;
        v.x = tf32f(fmaxf(c0[2], 0.f)); v.y = tf32f(fmaxf(c0[3], 0.f));
        *(float2*)(Xout + (e0 + 8 + g) * XP + n0 + 2 * tig) = v;
        v.x = tf32f(fmaxf(c1[0], 0.f)); v.y = tf32f(fmaxf(c1[1], 0.f));
        *(float2*)(Xout + (e0 + g) * XP + n1 + 2 * tig) = v;
        v.x = tf32f(fmaxf(c1[2], 0.f)); v.y = tf32f(fmaxf(c1[3], 0.f));
        *(float2*)(Xout + (e0 + 8 + g) * XP + n1 + 2 * tig) = v;
    }
}

// output layer: N=8 (3 valid), no relu, writes straight to gmem
template<int KC>
DINL void layer_out(const float* __restrict__ Xin, const float* __restrict__ Ws,
                    const float* __restrict__ Bs, float* __restrict__ out,
                    const int* __restrict__ ords, int cnt, int fi,
                    int e0, int g, int tig) {
    uint32_t a[KC][4];
    #pragma unroll
    for (int kc = 0; kc < KC; ++kc) {
        const float* xr = Xin + (e0 + g) * XP + kc * 8 + tig;
        a[kc][0] = __float_as_uint(xr[0]);
        a[kc][2] = __float_as_uint(xr[4]);
        a[kc][1] = __float_as_uint(xr[8 * XP]);
        a[kc][3] = __float_as_uint(xr[8 * XP + 4]);
    }
    float c0 = Bs[2 * tig], c1 = Bs[2 * tig + 1];
    float c2 = c0, c3 = c1;
    #pragma unroll
    for (int kc = 0; kc < KC; ++kc) {
        const float* w0 = Ws + g * XP + kc * 8 + tig;
        uint32_t b0 = __float_as_uint(w0[0]), b1 = __float_as_uint(w0[4]);
        mma8(c0, c1, c2, c3, a[kc][0], a[kc][1], a[kc][2], a[kc][3], b0, b1);
    }
    const int col0 = 2 * tig, col1 = 2 * tig + 1;
    const int e1 = e0 + g, e2 = e0 + 8 + g;
    if (e1 < cnt) {
        const int base = ords[e1] * (NFACT * OUT_F) + fi * OUT_F;
        if (col0 < OUT_F) out[base + col0] = c0;
        if (col1 < OUT_F) out[base + col1] = c1;
    }
    if (e2 < cnt) {
        const int base = ords[e2] * (NFACT * OUT_F) + fi * OUT_F;
        if (col0 < OUT_F) out[base + col0] = c2;
        if (col1 < OUT_F) out[base + col1] = c3;
    }
}

// ---------------- staging (row-major [n][k], tf32-rounded) ----------------
template<int H>
DINL void stage_wh(const float* __restrict__ Wg, float* __restrict__ Ws) {
    constexpr int Q = H / 4;
    for (int i = threadIdx.x; i < H * Q; i += NTHREADS) {
        int n = i / Q, k = (i - n * Q) * 4;
        float4 w = *(const float4*)(Wg + n * HID + k);
        Ws[n * XP + k + 0] = tf32f(w.x);
        Ws[n * XP + k + 1] = tf32f(w.y);
        Ws[n * XP + k + 2] = tf32f(w.z);
        Ws[n * XP + k + 3] = tf32f(w.w);
    }
}
template<int H>
DINL void stage_w0(const float* __restrict__ Wg, float* __restrict__ Ws) {
    for (int i = threadIdx.x; i < H * 8; i += NTHREADS) {
        int n = i >> 3, k = i & 7;
        Ws[n * XP + k] = (k < IN_F) ? tf32f(Wg[n * IN_F + k]) : 0.f;
    }
}
template<int H>
DINL void stage_w4(const float* __restrict__ Wg, float* __restrict__ Ws) {
    constexpr int Q = H / 4;
    for (int i = threadIdx.x; i < 8 * Q; i += NTHREADS) {
        int o = i / Q, k = (i - o * Q) * 4;
        float4 w = (o < OUT_F) ? *(const float4*)(Wg + o * HID + k)
                               : make_float4(0.f, 0.f, 0.f, 0.f);
        Ws[o * XP + k + 0] = tf32f(w.x);
        Ws[o * XP + k + 1] = tf32f(w.y);
        Ws[o * XP + k + 2] = tf32f(w.z);
        Ws[o * XP + k + 3] = tf32f(w.w);
    }
}

// ---------------- fused MLP kernel ----------------
template<int H>
DINL void mlp_body(const float* __restrict__ inp,
                   const float* __restrict__ W0, const float* __restrict__ b0,
                   const float* __restrict__ W1, const float* __restrict__ b1,
                   const float* __restrict__ W2, const float* __restrict__ b2,
                   const float* __restrict__ W3, const float* __restrict__ b3,
                   const float* __restrict__ W4, const float* __restrict__ b4,
                   float* __restrict__ out) {
    extern __shared__ float sm[];
    float* Xa = sm;                      // MT*XP
    float* Xb = Xa + MT * XP;            // MT*XP
    float* Ws = Xb + MT * XP;            // HID*XP
    float* Bs = Ws + HID * XP;           // HID (>=8)
    int*   ords = (int*)(Bs + HID);      // MT

    constexpr int KC = H / 8;
    constexpr int NC = H / 8;
    constexpr int fi = H / 32 - 1;

    const int tid = threadIdx.x;
    const int wid = tid >> 5;
    const int lane = tid & 31;
    const int g = lane >> 2, tig = lane & 3;
    const int e0 = wid * 16;

    const int m = blockIdx.y;
    const int off0 = g_offsets[m];
    const int off1 = g_offsets[m + 1];

    const float* Wg0 = W0 + m * (HID * IN_F);
    const float* WgH[3] = { W1 + m * (HID * HID), W2 + m * (HID * HID), W3 + m * (HID * HID) };
    const float* bgH[3] = { b1 + m * HID, b2 + m * HID, b3 + m * HID };
    const float* Wg4 = W4 + m * (OUT_F * HID);
    const float* bg4 = b4 + m * OUT_F;

    for (int tile = blockIdx.x; off0 + tile * MT < off1; tile += NT_X) {
        const int beg = off0 + tile * MT;
        const int cnt = min(MT, off1 - beg);

        for (int i = tid; i < MT; i += NTHREADS)
            ords[i] = (i < cnt) ? g_order[beg + i] : 0;
        __syncthreads();

        // inputs -> Xa cols 0..7 (tf32-rounded, zero pad)
        for (int i = tid; i < MT * 8; i += NTHREADS) {
            int e = i >> 3, c = i & 7;
            Xa[e * XP + c] = (c < IN_F) ? tf32f(inp[(size_t)ords[e] * IN_F + c]) : 0.f;
        }
        stage_w0<H>(Wg0, Ws);
        for (int i = tid; i < H; i += NTHREADS) Bs[i] = b0[m * HID + i];
        __syncthreads();

        layer_fc<1, NC>(Xa, Xb, Ws, Bs, e0, g, tig);     // L0: K=8
        __syncthreads();

        #pragma unroll
        for (int L = 0; L < 3; ++L) {
            stage_wh<H>(WgH[L], Ws);
            for (int i = tid; i < H; i += NTHREADS) Bs[i] = bgH[L][i];
            __syncthreads();
            if (L & 1) layer_fc<KC, NC>(Xa, Xb, Ws, Bs, e0, g, tig);
            else       layer_fc<KC, NC>(Xb, Xa, Ws, Bs, e0, g, tig);
            __syncthreads();
        }
        // after L0:Xb, L1:Xa, L2:Xb, L3:Xa  -> final hidden acts in Xa

        stage_w4<H>(Wg4, Ws);
        if (tid < 8) Bs[tid] = (tid < OUT_F) ? bg4[tid] : 0.f;
        __syncthreads();

        layer_out<KC>(Xa, Ws, Bs, out, ords, cnt, fi, e0, g, tig);
        __syncthreads();
    }
}

__global__ __launch_bounds__(NTHREADS, 1) void k_mlp_all(
    const float* __restrict__ inp,
    const float* __restrict__ W0, const float* __restrict__ b0,
    const float* __restrict__ W1, const float* __restrict__ b1,
    const float* __restrict__ W2, const float* __restrict__ b2,
    const float* __restrict__ W3, const float* __restrict__ b3,
    const float* __restrict__ W4, const float* __restrict__ b4,
    float* __restrict__ out) {
    switch (blockIdx.z) {
        case 0: mlp_body<32 >(inp, W0, b0, W1, b1, W2, b2, W3, b3, W4, b4, out); break;
        case 1: mlp_body<64 >(inp, W0, b0, W1, b1, W2, b2, W3, b3, W4, b4, out); break;
        case 2: mlp_body<96 >(inp, W0, b0, W1, b1, W2, b2, W3, b3, W4, b4, out); break;
        default: mlp_body<128>(inp, W0, b0, W1, b1, W2, b2, W3, b3, W4, b4, out); break;
    }
}

// ---------------- launch ----------------
extern "C" void kernel_launch(void* const* d_in, const int* in_sizes, int n_in,
                              void* d_out, int out_size) {
    const float* inp = (const float*)d_in[0];
    const float* W0  = (const float*)d_in[1];
    const float* b0  = (const float*)d_in[2];
    const float* W1  = (const float*)d_in[3];
    const float* b1  = (const float*)d_in[4];
    const float* W2  = (const float*)d_in[5];
    const float* b2  = (const float*)d_in[6];
    const float* W3  = (const float*)d_in[7];
    const float* b3  = (const float*)d_in[8];
    const float* W4  = (const float*)d_in[9];
    const float* b4  = (const float*)d_in[10];
    float* out = (float*)d_out;

    k_zero<<<1, 64>>>();
    k_select<<<B / NTHREADS, NTHREADS>>>(inp, out);
    k_fill<<<(B * NM / 4) / NTHREADS, NTHREADS>>>(out);
    k_scan<<<1, 64>>>();
    k_scatter<<<B / NTHREADS, NTHREADS>>>();

    size_t smem = (size_t)(2 * MT * XP + HID * XP + HID) * sizeof(float) + MT * sizeof(int);
    cudaFuncSetAttribute(k_mlp_all, cudaFuncAttributeMaxDynamicSharedMemorySize, (int)smem);
    dim3 grid(NT_X, NM, NFACT);
    k_mlp_all<<<grid, NTHREADS, smem>>>(inp, W0, b0, W1, b1, W2, b2, W3, b3, W4, b4, out);
}